// round 5
// baseline (speedup 1.0000x reference)
#include <cuda_runtime.h>
#include <math.h>

// FlowLenia step: SX=SY=256, C=3, K=15, DD=5, DT=0.2, SIGMA=0.65
// out = [newA (256*256*3) | newP (256*256*15)] float32

#define NX 256
#define NC 3
#define NK 15
#define NP 8                    // ceil(15/2) packed real pairs
#define DTc 0.2f
#define SIGMAc 0.65f
#define MAc 4.35f               // DD - SIGMA
#define INV4S2 (1.0f/(4.0f*0.65f*0.65f))
#define SUPP 1.15f              // 0.5 + SIGMA
#define IDX(i) ((i) + ((i) >> 4))   // skew pad, max 271
#define FSTR 273                    // float2 stride per FFT buffer

static __device__ float2 g_fA[NC*NX*NX];     // [c][x][y] planar complex
static __device__ float2 g_G [NX*NX*NP];     // [x][y][j]  8 pairs contiguous
static __device__ float  g_Uc[NX*NX*NC];     // [y][x][c]

__device__ __forceinline__ int rev4(int i) {
    return ((i & 3) << 6) | ((i & 0xC) << 2) | ((i >> 2) & 0xC) | ((i >> 6) & 3);
}
__device__ __forceinline__ float2 cmul(float2 a, float2 b) {
    return make_float2(a.x*b.x - a.y*b.y, a.x*b.y + a.y*b.x);
}

// Per-block twiddle table in smem: tw[j] = exp(-2*pi*i*j/256)
__device__ __forceinline__ void tw_init_smem(float2* tw, int tid, int nthr) {
    for (int j = tid; j < 256; j += nthr) {
        float sv, cv;
        sincospif(-(float)j * (1.0f/128.0f), &sv, &cv);
        tw[j] = make_float2(cv, sv);
    }
}

// Warp-private in-shared 256-pt radix-4 DIT FFT: ONE warp owns the whole buffer,
// 8 elements per lane (2 butterfly groups per stage). Only __syncwarp between
// stages — no block barriers. Input digit-reversed via IDX. Caller must
// __syncthreads after producing s/tw and after this before cross-warp reads.
template<bool INV>
__device__ __forceinline__ void fft256_r4w(float2* s, const float2* tw, int lane) {
#pragma unroll
    for (int m = 0; m < 4; m++) {
        __syncwarp();
#pragma unroll
        for (int gg = 0; gg < 2; gg++) {
            int t = lane + 32*gg;
            int q    = 1 << (2*m);
            int p    = t & (q - 1);
            int grp  = t >> (2*m);
            int base = grp*(q << 2) + p;
            int ts   = 64 >> (2*m);
            float2 w1 = tw[p*ts];
            float2 w2 = tw[2*p*ts];
            float2 w3 = tw[3*p*ts];
            if (INV) { w1.y = -w1.y; w2.y = -w2.y; w3.y = -w3.y; }
            float2 x0 = s[IDX(base)];
            float2 t1 = cmul(s[IDX(base +   q)], w1);
            float2 t2 = cmul(s[IDX(base + 2*q)], w2);
            float2 t3 = cmul(s[IDX(base + 3*q)], w3);
            float2 b0 = make_float2(x0.x + t2.x, x0.y + t2.y);
            float2 b1 = make_float2(x0.x - t2.x, x0.y - t2.y);
            float2 b2 = make_float2(t1.x + t3.x, t1.y + t3.y);
            float2 b3 = make_float2(t1.x - t3.x, t1.y - t3.y);
            float2 ib3 = INV ? make_float2(-b3.y, b3.x) : make_float2(b3.y, -b3.x);
            s[IDX(base)]        = make_float2(b0.x + b2.x, b0.y + b2.y);
            s[IDX(base +   q)]  = make_float2(b1.x + ib3.x, b1.y + ib3.y);
            s[IDX(base + 2*q)]  = make_float2(b0.x - b2.x, b0.y - b2.y);
            s[IDX(base + 3*q)]  = make_float2(b1.x - ib3.x, b1.y - ib3.y);
        }
    }
    __syncwarp();
}

// S1: FFT along y. block = 192 thr (6 warps) = 2 rows x 3 channels.
__global__ void s1_fft_y(const float* __restrict__ A) {
    __shared__ float2 sm[6][FSTR];
    __shared__ float2 tw[256];
    int tid = threadIdx.x, w = tid >> 5, lane = tid & 31;
    int x = blockIdx.x*2 + (w >= 3), c = w - (w >= 3 ? 3 : 0);
    tw_init_smem(tw, tid, 192);
    float2* s = sm[w];
#pragma unroll
    for (int jj = 0; jj < 8; jj++) {
        int i = lane + 32*jj;
        s[IDX(rev4(i))] = make_float2(A[(x*NX + i)*NC + c], 0.f);
    }
    __syncthreads();               // tw table ready
    fft256_r4w<false>(s, tw, lane);
#pragma unroll
    for (int jj = 0; jj < 8; jj++) {
        int i = lane + 32*jj;
        g_fA[c*NX*NX + x*NX + i] = s[IDX(i)];
    }
}

// S2: FFT along x. block = 128 thr (4 warps) = 4 ky-columns of one channel.
__global__ void s2_fft_x() {
    __shared__ float2 sm[4][FSTR];
    __shared__ float2 tw[256];
    int c = blockIdx.y, y0 = blockIdx.x * 4;
    int tid = threadIdx.x, w = tid >> 5, lane = tid & 31;
    tw_init_smem(tw, tid, 128);
    int base = c*NX*NX;
    for (int e = tid; e < 1024; e += 128) {
        int x = e >> 2, yy = e & 3;
        sm[yy][IDX(rev4(x))] = g_fA[base + x*NX + y0 + yy];
    }
    __syncthreads();
    fft256_r4w<false>(sm[w], tw, lane);
    __syncthreads();
    for (int e = tid; e < 1024; e += 128) {
        int x = e >> 2, yy = e & 3;
        g_fA[base + x*NX + y0 + yy] = sm[yy][IDX(x)];
    }
}

// S3: multiply by fK + inverse FFT along y. block = 256 thr (8 warps = 8 pairs).
// H_j = fK_{2j}*fA_{c1} + i*fK_{2j+1}*fA_{c2}; Re/Im of ifft2 give U_{2j}, U_{2j+1}.
__global__ void s3_mul_ifft_y(const float* __restrict__ fKr, const float* __restrict__ fKi) {
    __shared__ float2 sm[NP][FSTR];
    __shared__ float2 sfA[NC][NX];
    __shared__ float2 tw[256];
    int x = blockIdx.x;
    int tid = threadIdx.x, w = tid >> 5, lane = tid & 31;
    tw_init_smem(tw, tid, 256);
    for (int e = tid; e < NC*NX; e += 256) {
        int c = e >> 8, y = e & 255;
        sfA[c][y] = g_fA[c*NX*NX + x*NX + y];
    }
    __syncthreads();
    for (int e = tid; e < 2048; e += 256) {
        int y = e >> 3, jj = e & 7;
        int k1 = 2*jj;
        int idx = (x*NX + y)*NK;
        float2 a1 = sfA[k1 % NC][y];
        float kr = fKr[idx + k1], ki = fKi[idx + k1];
        float2 H = make_float2(kr*a1.x - ki*a1.y, kr*a1.y + ki*a1.x);
        if (k1 + 1 < NK) {
            float2 a2 = sfA[(k1+1) % NC][y];
            float kr2 = fKr[idx + k1 + 1], ki2 = fKi[idx + k1 + 1];
            float zr = kr2*a2.x - ki2*a2.y;
            float zi = kr2*a2.y + ki2*a2.x;
            H.x -= zi; H.y += zr;
        }
        sm[jj][IDX(rev4(y))] = H;
    }
    __syncthreads();
    fft256_r4w<true>(sm[w], tw, lane);
    __syncthreads();
    for (int e = tid; e < 2048; e += 256) {
        int y = e >> 3, jj = e & 7;
        g_G[(x*NX + y)*NP + jj] = sm[jj][IDX(y)];
    }
}

// S4: inverse FFT along x + growth*P + channel-sum. block = 256 thr (8 warps = 8 pairs).
__global__ void s4_ifft_x_growth(const float* __restrict__ P,
                                 const float* __restrict__ mArr,
                                 const float* __restrict__ sArr) {
    __shared__ float2 sm[NP][FSTR];
    __shared__ float  sP[NX*17];
    __shared__ float2 tw[256];
    int y = blockIdx.x;
    int tid = threadIdx.x, w = tid >> 5, lane = tid & 31;
    tw_init_smem(tw, tid, 256);
    for (int e = tid; e < 2048; e += 256) {
        int xx = e >> 3, jj = e & 7;
        sm[jj][IDX(rev4(xx))] = g_G[(xx*NX + y)*NP + jj];
    }
    for (int e = tid; e < NX*NK; e += 256) {
        int xx = e / NK, k = e - xx*NK;
        sP[xx*17 + k] = P[(xx*NX + y)*NK + k];
    }
    __syncthreads();
    fft256_r4w<true>(sm[w], tw, lane);

    int k1 = 2*w, k2 = 2*w + 1;
    float m1 = mArr[k1], s1 = sArr[k1];
    float inv1 = 1.f / (2.f * s1 * s1);
    float m2 = 0.f, inv2 = 0.f;
    if (k2 < NK) { m2 = mArr[k2]; float s2 = sArr[k2]; inv2 = 1.f / (2.f * s2 * s2); }
#pragma unroll
    for (int jj2 = 0; jj2 < 8; jj2++) {
        int xx = lane + 32*jj2;
        float2 v = sm[w][IDX(xx)];
        float u1 = v.x * (1.f / 65536.f);
        float d1 = u1 - m1;
        sP[xx*17 + k1] *= (2.f * expf(-d1*d1*inv1) - 1.f);
        if (k2 < NK) {
            float u2 = v.y * (1.f / 65536.f);
            float d2 = u2 - m2;
            sP[xx*17 + k2] *= (2.f * expf(-d2*d2*inv2) - 1.f);
        }
    }
    __syncthreads();
    for (int e = tid; e < NX*NC; e += 256) {
        int xx = e / NC, c = e - xx*NC;
        const float* u = sP + xx*17;
        g_Uc[(y*NX + xx)*NC + c] = u[c] + u[c+3] + u[c+6] + u[c+9] + u[c+12];
    }
}

// Fused sobel + mus + reintegration. Output tile 8(x) x 16(y) per 128-thread block.
// Records: [mu0(3), mu1(3), A(3), P(15)] = 24 floats.
// Only |shift|<=2 contributes (support 1.15, |DT*F|<=0.87); sentinel mus at edges.
#define TXo 8
#define TYo 16
__global__ void fused_flow(const float* __restrict__ A, const float* __restrict__ P,
                           float* __restrict__ outA, float* __restrict__ outP) {
    __shared__ __align__(16) float rec[240*24];   // 12 x 20 records
    __shared__ float sUc[14*22*3];
    __shared__ float sAs[14*22];
    int tid = threadIdx.x;                        // 128
    int y0 = blockIdx.x * TYo, x0 = blockIdx.y * TXo;

    for (int e = tid; e < 14*22; e += 128) {
        int i = e / 22, j = e - i*22;
        int gx = x0 - 3 + i, gy = y0 - 3 + j;
        float u0 = 0.f, u1 = 0.f, u2 = 0.f, as = 0.f;
        if (gx >= 0 && gx < NX && gy >= 0 && gy < NX) {
            int bU = (gy*NX + gx)*NC;
            u0 = g_Uc[bU]; u1 = g_Uc[bU+1]; u2 = g_Uc[bU+2];
            int bA = (gx*NX + gy)*NC;
            as = A[bA] + A[bA+1] + A[bA+2];
        }
        sUc[e*3+0] = u0; sUc[e*3+1] = u1; sUc[e*3+2] = u2;
        sAs[e] = as;
    }
    __syncthreads();

    for (int e = tid; e < 240; e += 128) {
        int i = e / 20, j = e - i*20;
        int gx = x0 - 2 + i, gy = y0 - 2 + j;
        float* r = rec + e*24;
        if (gx >= 0 && gx < NX && gy >= 0 && gy < NX) {
            int si = i + 1, sj = j + 1;
            int rm = (si-1)*22 + sj, rp = (si+1)*22 + sj, r0 = si*22 + sj;
            float cg0 = (sAs[rp-1] + 2.f*sAs[rp] + sAs[rp+1])
                      - (sAs[rm-1] + 2.f*sAs[rm] + sAs[rm+1]);
            float cg1 = (sAs[rm+1] + 2.f*sAs[r0+1] + sAs[rp+1])
                      - (sAs[rm-1] + 2.f*sAs[r0-1] + sAs[rp-1]);
            int bA = (gx*NX + gy)*NC;
            float p0 = gx + 0.5f, p1 = gy + 0.5f;
#pragma unroll
            for (int c = 0; c < NC; c++) {
                float f0 = (sUc[(rp-1)*3+c] + 2.f*sUc[rp*3+c] + sUc[(rp+1)*3+c])
                         - (sUc[(rm-1)*3+c] + 2.f*sUc[rm*3+c] + sUc[(rm+1)*3+c]);
                float f1 = (sUc[(rm+1)*3+c] + 2.f*sUc[(r0+1)*3+c] + sUc[(rp+1)*3+c])
                         - (sUc[(rm-1)*3+c] + 2.f*sUc[(r0-1)*3+c] + sUc[(rp-1)*3+c]);
                float ac = A[bA + c];
                float ah = ac * 0.5f;
                float alpha = fminf(ah*ah, 1.f);
                float F0 = fminf(fmaxf(f0*(1.f-alpha) - cg0*alpha, -MAc), MAc);
                float F1 = fminf(fmaxf(f1*(1.f-alpha) - cg1*alpha, -MAc), MAc);
                r[c]   = fminf(fmaxf(p0 + DTc*F0, SIGMAc), (float)NX - SIGMAc);
                r[3+c] = fminf(fmaxf(p1 + DTc*F1, SIGMAc), (float)NX - SIGMAc);
                r[6+c] = ac;
            }
        } else {
#pragma unroll
            for (int c = 0; c < 6; c++) r[c] = -1e9f;
            r[6] = r[7] = r[8] = 0.f;
        }
    }
    for (int e = tid; e < 240*NK; e += 128) {
        int pix = e / NK, k = e - pix*NK;
        int i = pix / 20, j = pix - i*20;
        int gx = x0 - 2 + i, gy = y0 - 2 + j;
        float v = 0.f;
        if (gx >= 0 && gx < NX && gy >= 0 && gy < NX)
            v = P[(gx*NX + gy)*NK + k];
        rec[pix*24 + 9 + k] = v;
    }
    __syncthreads();

    int ty = tid & 15, tx = tid >> 4;
    int x = x0 + tx, y = y0 + ty;
    float p0 = x + 0.5f, p1 = y + 0.5f;
    float accA0 = 0.f, accA1 = 0.f, accA2 = 0.f, accW = 0.f;
    float accP[NK];
#pragma unroll
    for (int k = 0; k < NK; k++) accP[k] = 0.f;

#pragma unroll
    for (int dx = -2; dx <= 2; dx++) {
#pragma unroll
        for (int dy = -2; dy <= 2; dy++) {
            int ridx = (tx + 2 - dx)*20 + (ty + 2 - dy);
            const float4* r4 = (const float4*)(rec + ridx*24);
            float4 q0 = r4[0];
            float4 q1 = r4[1];
            float4 q2 = r4[2];
            float s00 = fminf(fmaxf(SUPP - fabsf(p0 - q0.x), 0.f), 1.f);
            float s01 = fminf(fmaxf(SUPP - fabsf(p0 - q0.y), 0.f), 1.f);
            float s02 = fminf(fmaxf(SUPP - fabsf(p0 - q0.z), 0.f), 1.f);
            float s10 = fminf(fmaxf(SUPP - fabsf(p1 - q0.w), 0.f), 1.f);
            float s11 = fminf(fmaxf(SUPP - fabsf(p1 - q1.x), 0.f), 1.f);
            float s12 = fminf(fmaxf(SUPP - fabsf(p1 - q1.y), 0.f), 1.f);
            float v0 = q1.z * (s00*s10*INV4S2);
            float v1 = q1.w * (s01*s11*INV4S2);
            float v2 = q2.x * (s02*s12*INV4S2);
            accA0 += v0; accA1 += v1; accA2 += v2;
            float suma = v0 + v1 + v2;
            if (suma > 0.f) {
                float w = expf(suma) - 1.f;
                accW += w;
                accP[0] += w*q2.y; accP[1] += w*q2.z; accP[2] += w*q2.w;
                float4 q3 = r4[3], q4 = r4[4], q5 = r4[5];
                accP[3] += w*q3.x; accP[4] += w*q3.y; accP[5] += w*q3.z; accP[6] += w*q3.w;
                accP[7] += w*q4.x; accP[8] += w*q4.y; accP[9] += w*q4.z; accP[10] += w*q4.w;
                accP[11] += w*q5.x; accP[12] += w*q5.y; accP[13] += w*q5.z; accP[14] += w*q5.w;
            }
        }
    }

    int o = x*NX + y;
    outA[o*NC + 0] = accA0; outA[o*NC + 1] = accA1; outA[o*NC + 2] = accA2;
    float inv = 1.f / (accW + 1e-10f);
#pragma unroll
    for (int k = 0; k < NK; k++) outP[o*NK + k] = accP[k] * inv;
}

extern "C" void kernel_launch(void* const* d_in, const int* in_sizes, int n_in,
                              void* d_out, int out_size) {
    const float* A   = (const float*)d_in[0];
    const float* P   = (const float*)d_in[1];
    const float* fKr = (const float*)d_in[2];
    const float* fKi = (const float*)d_in[3];
    const float* m   = (const float*)d_in[4];
    const float* s   = (const float*)d_in[5];
    float* outA = (float*)d_out;
    float* outP = outA + NX*NX*NC;

    s1_fft_y         <<<128, 192>>>(A);
    s2_fft_x         <<<dim3(64, NC), 128>>>();
    s3_mul_ifft_y    <<<NX, 256>>>(fKr, fKi);
    s4_ifft_x_growth <<<NX, 256>>>(P, m, s);
    fused_flow       <<<dim3(16, 32), 128>>>(A, P, outA, outP);
}